// round 9
// baseline (speedup 1.0000x reference)
#include <cuda_runtime.h>

// ---------------- Problem constants ----------------
#define BATCH    512
#define FEAT     1024
#define O1       2000
#define O2       1000
#define NLUT     64
#define NCLS     10
#define TAU      3.3333333f

#define RG       8
#define NG       (BATCH / RG)       // 64

#define A_OSPL   4
#define A_OUT    (O1 / A_OSPL)      // 500

// kB: 5 output slices -> 200 outputs (= 2 classes) per CTA, 320 CTAs total.
// 3 CTAs/SM (64KB smem, 448 thr) -> 444 slots -> single 0.72 wave, no tail.
#define B_OSPL   5
#define B_OUT    (O2 / B_OSPL)      // 200
#define NPAIR    (B_OUT / 2)        // 100 pairs (p, p+100)
#define L2PS     66                 // padded u64 stride per LUT pair (528B)
#define BTHREADS 448

// ---------------- Device scratch ----------------
__device__ float g_h1[NG * O1 * RG];      // 4 MB, layout [g][o][r]

// ---------------- f32x2 helpers ----------------
__device__ __forceinline__ unsigned long long pk2(float lo, float hi) {
    unsigned long long r;
    asm("mov.b64 %0, {%1, %2};" : "=l"(r) : "f"(lo), "f"(hi));
    return r;
}
__device__ __forceinline__ void upk2(float& lo, float& hi, unsigned long long v) {
    asm("mov.b64 {%0, %1}, %2;" : "=f"(lo), "=f"(hi) : "l"(v));
}
__device__ __forceinline__ unsigned long long fma2(unsigned long long a,
                                                   unsigned long long b,
                                                   unsigned long long c) {
    unsigned long long d;
    asm("fma.rn.f32x2 %0, %1, %2, %3;" : "=l"(d) : "l"(a), "l"(b), "l"(c));
    return d;
}
__device__ __forceinline__ unsigned long long lerp2(unsigned long long a,
                                                    unsigned long long b,
                                                    unsigned long long x,
                                                    unsigned long long nx) {
    return fma2(x, b, fma2(nx, a, a));
}

// ============ Kernel 1: thermometer + layer 1 gather ============
// grid 64*4 = 256 CTAs, 512 threads. thr staged to smem (confirmed win R8).
__global__ __launch_bounds__(512)
void k01_layer1(const float* __restrict__ x,     const float* __restrict__ thr,
                const float* __restrict__ luts1, const int* __restrict__ idx1)
{
    __shared__ float    s_thr[FEAT * 3];      // 12 KB
    __shared__ unsigned s_bits[RG * 97];      // 3.1 KB
    __shared__ int      s_idx[A_OUT * 6];     // 12 KB

    const int g     = blockIdx.x >> 2;
    const int os    = blockIdx.x & 3;
    const int obase = os * A_OUT;
    const int tid   = threadIdx.x;
    const int lane  = tid & 31;

    for (int i = tid; i < FEAT * 3 / 4; i += 512)
        ((float4*)s_thr)[i] = __ldg((const float4*)thr + i);
    for (int i = tid; i < A_OUT * 6; i += 512)
        s_idx[i] = __ldg(idx1 + obase * 6 + i);
    __syncthreads();

    for (int i = tid; i < RG * FEAT; i += 512) {
        const int r = i >> 10;
        const int f = i & 1023;
        float xv = __ldg(x + (g * RG + r) * FEAT + f);
        float t0 = s_thr[f * 3 + 0];
        float t1 = s_thr[f * 3 + 1];
        float t2 = s_thr[f * 3 + 2];
        unsigned b0 = __ballot_sync(0xFFFFFFFFu, xv > t0);
        unsigned b1 = __ballot_sync(0xFFFFFFFFu, xv > t1);
        unsigned b2 = __ballot_sync(0xFFFFFFFFu, xv > t2);
        if (lane == 0) {
            unsigned* wp = s_bits + r * 97 + (f >> 5);
            wp[0]  = b0;
            wp[32] = b1;
            wp[64] = b2;
        }
    }
    __syncthreads();

    #pragma unroll 2
    for (int t = tid; t < A_OUT * RG; t += 512) {
        const int ol = t >> 3;
        const int r  = t & 7;
        const unsigned* bp = s_bits + r * 97;
        int code = 0;
        #pragma unroll
        for (int k = 0; k < 6; k++) {
            unsigned i  = (unsigned)s_idx[ol * 6 + k];
            unsigned f  = i / 3u;
            unsigned tt = i - f * 3u;
            unsigned wv = bp[tt * 32 + (f >> 5)];
            code = (code << 1) | (int)((wv >> (f & 31)) & 1u);
        }
        g_h1[(g * O1 + obase + ol) * RG + r] =
            __ldg(luts1 + (obase + ol) * NLUT + code);
    }
}

// ============ Kernel 2: layer 2 interp + class sums ============
// grid 64*5 = 320 CTAs, 448 threads, 64 KB smem, 3 CTAs/SM -> single wave.
// Compute thread handles 2 pairs sequentially; both pairs' x prefetched in
// one burst after the barrier (R7 ordering, measured better than hoisting).
__global__ __launch_bounds__(BTHREADS, 3)
void kB_layer2(const float* __restrict__ luts2, const int* __restrict__ idx2,
               float* __restrict__ out)
{
    extern __shared__ char smem[];
    unsigned long long* s_l2p = (unsigned long long*)smem;        // 100*66 u64 (52.8 KB)
    int*                s_idx = (int*)(s_l2p + NPAIR * L2PS);     // 1200 i (4.8 KB)
    float*              s_h2  = (float*)(s_idx + B_OUT * 6);      // 1600 f (6.4 KB)

    const int g     = blockIdx.x / B_OSPL;
    const int os    = blockIdx.x % B_OSPL;
    const int obase = os * B_OUT;
    const int tid   = threadIdx.x;

    // ---- stage luts2 slice: pair-interleaved, level-5 pairs as (a, b-a) ----
    for (int i = tid; i < NPAIR * (NLUT / 4); i += BTHREADS) {
        const int pp = i >> 4, q = i & 15;
        float4 a = __ldg((const float4*)(luts2 + (obase + pp) * NLUT) + q);
        float4 b = __ldg((const float4*)(luts2 + (obase + NPAIR + pp) * NLUT) + q);
        unsigned long long* d = s_l2p + pp * L2PS + q * 4;
        d[0] = pk2(a.x, b.x);
        d[1] = pk2(a.y - a.x, b.y - b.x);
        d[2] = pk2(a.z, b.z);
        d[3] = pk2(a.w - a.z, b.w - b.z);
    }
    for (int i = tid; i < B_OUT * 6; i += BTHREADS)
        s_idx[i] = __ldg(idx2 + obase * 6 + i);
    __syncthreads();

    if (tid < RG * NPAIR / 2) {              // 400 compute threads
        const int q = tid >> 3;              // pair-couple id: pairs 2q, 2q+1
        const int r = tid & 7;               // row within group
        const float* h1g = g_h1 + (size_t)g * O1 * RG + r;

        // ---- burst-prefetch x for BOTH pairs (24 LDGs, full MLP) ----
        float xa[2][6], xb[2][6];
        #pragma unroll
        for (int pi = 0; pi < 2; pi++) {
            const int p = 2 * q + pi;
            const int* iA = s_idx + p * 6;
            const int* iB = s_idx + (p + NPAIR) * 6;
            #pragma unroll
            for (int k = 0; k < 6; k++) {
                xa[pi][k] = __ldg(h1g + iA[k] * RG);
                xb[pi][k] = __ldg(h1g + iB[k] * RG);
            }
        }

        #pragma unroll
        for (int pi = 0; pi < 2; pi++) {
            const int p = 2 * q + pi;
            const unsigned long long* Lp = s_l2p + p * L2PS;

            unsigned long long xp5 = pk2(xa[pi][5], xb[pi][5]);
            unsigned long long xp4 = pk2(xa[pi][4], xb[pi][4]);
            unsigned long long xn4 = pk2(-xa[pi][4], -xb[pi][4]);
            unsigned long long xp3 = pk2(xa[pi][3], xb[pi][3]);
            unsigned long long xn3 = pk2(-xa[pi][3], -xb[pi][3]);
            unsigned long long xp2 = pk2(xa[pi][2], xb[pi][2]);
            unsigned long long xn2 = pk2(-xa[pi][2], -xb[pi][2]);

            unsigned long long u[4];
            #pragma unroll
            for (int t = 0; t < 4; t++) {
                const unsigned long long* Lt = Lp + 16 * t;
                ulonglong2 c;
                unsigned long long w0, w1, v0, v1, h0, h1v;
                c = *(const ulonglong2*)(Lt + 0);  w0 = fma2(xp5, c.y, c.x);
                c = *(const ulonglong2*)(Lt + 2);  w1 = fma2(xp5, c.y, c.x);
                v0 = lerp2(w0, w1, xp4, xn4);
                c = *(const ulonglong2*)(Lt + 4);  w0 = fma2(xp5, c.y, c.x);
                c = *(const ulonglong2*)(Lt + 6);  w1 = fma2(xp5, c.y, c.x);
                v1 = lerp2(w0, w1, xp4, xn4);
                h0 = lerp2(v0, v1, xp3, xn3);
                c = *(const ulonglong2*)(Lt + 8);  w0 = fma2(xp5, c.y, c.x);
                c = *(const ulonglong2*)(Lt + 10); w1 = fma2(xp5, c.y, c.x);
                v0 = lerp2(w0, w1, xp4, xn4);
                c = *(const ulonglong2*)(Lt + 12); w0 = fma2(xp5, c.y, c.x);
                c = *(const ulonglong2*)(Lt + 14); w1 = fma2(xp5, c.y, c.x);
                v1 = lerp2(w0, w1, xp4, xn4);
                h1v = lerp2(v0, v1, xp3, xn3);
                u[t] = lerp2(h0, h1v, xp2, xn2);
            }
            unsigned long long xp1 = pk2(xa[pi][1], xb[pi][1]);
            unsigned long long xn1 = pk2(-xa[pi][1], -xb[pi][1]);
            unsigned long long t0 = lerp2(u[0], u[1], xp1, xn1);
            unsigned long long t1 = lerp2(u[2], u[3], xp1, xn1);
            unsigned long long xp0 = pk2(xa[pi][0], xb[pi][0]);
            unsigned long long xn0 = pk2(-xa[pi][0], -xb[pi][0]);
            unsigned long long res = lerp2(t0, t1, xp0, xn0);

            float hA, hB;
            upk2(hA, hB, res);
            s_h2[p * RG + r]           = hA;    // class os*2   contribution
            s_h2[(p + NPAIR) * RG + r] = hB;    // class os*2+1 contribution
        }
    }
    __syncthreads();

    // ---- deterministic fixed-order class sums: 2 classes x 8 rows ----
    if (tid < 2 * RG) {
        const int c = tid >> 3;
        const int r = tid & 7;
        const float* hp = s_h2 + c * NPAIR * RG + r;
        float s0 = 0.f, s1 = 0.f;
        #pragma unroll 4
        for (int j = 0; j < NPAIR; j += 2) {
            s0 += hp[(j + 0) * RG];
            s1 += hp[(j + 1) * RG];
        }
        out[(g * RG + r) * NCLS + os * 2 + c] = (s0 + s1) / TAU;
    }
}

// ================== launch ==================
extern "C" void kernel_launch(void* const* d_in, const int* in_sizes, int n_in,
                              void* d_out, int out_size)
{
    const float* x      = (const float*)d_in[0];
    const float* thr    = (const float*)d_in[1];
    const float* luts1  = (const float*)d_in[2];
    const int*   idx1   = (const int*)  d_in[3];
    const float* luts2  = (const float*)d_in[4];
    const int*   idx2   = (const int*)  d_in[5];
    float*       out    = (float*)d_out;

    const int smemB = NPAIR * L2PS * 8 + B_OUT * 6 * 4 + B_OUT * RG * 4;
    static bool attr_set = false;
    if (!attr_set) {
        cudaFuncSetAttribute(kB_layer2, cudaFuncAttributeMaxDynamicSharedMemorySize, smemB);
        attr_set = true;
    }

    k01_layer1<<<NG * A_OSPL, 512>>>(x, thr, luts1, idx1);
    kB_layer2<<<NG * B_OSPL, BTHREADS, smemB>>>(luts2, idx2, out);
}

// round 10
// speedup vs baseline: 1.0089x; 1.0089x over previous
#include <cuda_runtime.h>

// ---------------- Problem constants ----------------
#define BATCH    512
#define FEAT     1024
#define O1       2000
#define O2       1000
#define NLUT     64
#define NCLS     10
#define TAU      3.3333333f

#define RG       8
#define NG       (BATCH / RG)       // 64

// kA: 8 output slices -> 512 CTAs (3.46 resident CTAs/SM vs 1.73 at 4)
#define A_OSPL   8
#define A_OUT    (O1 / A_OSPL)      // 250

// kB (R7 config, measured 12.96us): 10 slices, 640 CTAs, 4 CTAs/SM
#define B_OSPL   10
#define B_OUT    (O2 / B_OSPL)      // 100 = 1 class
#define NPAIR    (B_OUT / 2)        // 50
#define L2PS     66                 // padded u64 stride per LUT pair
#define BTHREADS 448

// ---------------- Device scratch ----------------
__device__ float g_h1[NG * O1 * RG];      // 4 MB, layout [g][o][r]

// ---------------- f32x2 helpers ----------------
__device__ __forceinline__ unsigned long long pk2(float lo, float hi) {
    unsigned long long r;
    asm("mov.b64 %0, {%1, %2};" : "=l"(r) : "f"(lo), "f"(hi));
    return r;
}
__device__ __forceinline__ void upk2(float& lo, float& hi, unsigned long long v) {
    asm("mov.b64 {%0, %1}, %2;" : "=f"(lo), "=f"(hi) : "l"(v));
}
__device__ __forceinline__ unsigned long long fma2(unsigned long long a,
                                                   unsigned long long b,
                                                   unsigned long long c) {
    unsigned long long d;
    asm("fma.rn.f32x2 %0, %1, %2, %3;" : "=l"(d) : "l"(a), "l"(b), "l"(c));
    return d;
}
__device__ __forceinline__ unsigned long long lerp2(unsigned long long a,
                                                    unsigned long long b,
                                                    unsigned long long x,
                                                    unsigned long long nx) {
    return fma2(x, b, fma2(nx, a, a));
}

// ============ Kernel 1: thermometer + layer 1 gather ============
// grid 64*8 = 512 CTAs, 512 threads. thr staged to smem (R8 win).
__global__ __launch_bounds__(512)
void k01_layer1(const float* __restrict__ x,     const float* __restrict__ thr,
                const float* __restrict__ luts1, const int* __restrict__ idx1)
{
    __shared__ float    s_thr[FEAT * 3];      // 12 KB
    __shared__ unsigned s_bits[RG * 97];      // 3.1 KB
    __shared__ int      s_idx[A_OUT * 6];     // 6 KB

    const int g     = blockIdx.x >> 3;
    const int os    = blockIdx.x & 7;
    const int obase = os * A_OUT;
    const int tid   = threadIdx.x;
    const int lane  = tid & 31;

    for (int i = tid; i < FEAT * 3 / 4; i += 512)
        ((float4*)s_thr)[i] = __ldg((const float4*)thr + i);
    for (int i = tid; i < A_OUT * 6; i += 512)
        s_idx[i] = __ldg(idx1 + obase * 6 + i);
    __syncthreads();

    for (int i = tid; i < RG * FEAT; i += 512) {
        const int r = i >> 10;
        const int f = i & 1023;
        float xv = __ldg(x + (g * RG + r) * FEAT + f);
        float t0 = s_thr[f * 3 + 0];
        float t1 = s_thr[f * 3 + 1];
        float t2 = s_thr[f * 3 + 2];
        unsigned b0 = __ballot_sync(0xFFFFFFFFu, xv > t0);
        unsigned b1 = __ballot_sync(0xFFFFFFFFu, xv > t1);
        unsigned b2 = __ballot_sync(0xFFFFFFFFu, xv > t2);
        if (lane == 0) {
            unsigned* wp = s_bits + r * 97 + (f >> 5);
            wp[0]  = b0;
            wp[32] = b1;
            wp[64] = b2;
        }
    }
    __syncthreads();

    #pragma unroll 2
    for (int t = tid; t < A_OUT * RG; t += 512) {
        const int ol = t >> 3;
        const int r  = t & 7;
        const unsigned* bp = s_bits + r * 97;
        int code = 0;
        #pragma unroll
        for (int k = 0; k < 6; k++) {
            unsigned i  = (unsigned)s_idx[ol * 6 + k];
            unsigned f  = i / 3u;
            unsigned tt = i - f * 3u;
            unsigned wv = bp[tt * 32 + (f >> 5)];
            code = (code << 1) | (int)((wv >> (f & 31)) & 1u);
        }
        g_h1[(g * O1 + obase + ol) * RG + r] =
            __ldg(luts1 + (obase + ol) * NLUT + code);
    }
}

// ============ Kernel 2: layer 2 interp + one class sum per CTA ============
// Exact R7 configuration (measured 12.96us): 640 CTAs, 448 threads,
// ~32 KB smem, 4 CTAs/SM, 32 regs; x loads after barrier, x1/x0 lazy.
__global__ __launch_bounds__(BTHREADS, 4)
void kB_layer2(const float* __restrict__ luts2, const int* __restrict__ idx2,
               float* __restrict__ out)
{
    extern __shared__ char smem[];
    unsigned long long* s_l2p = (unsigned long long*)smem;        // 50*66 u64 (26.4 KB)
    int*                s_idx = (int*)(s_l2p + NPAIR * L2PS);     // 600 i (2.4 KB)
    float*              s_h2  = (float*)(s_idx + B_OUT * 6);      // 800 f (3.2 KB)

    const int g     = blockIdx.x / B_OSPL;
    const int os    = blockIdx.x % B_OSPL;
    const int obase = os * B_OUT;
    const int tid   = threadIdx.x;

    // ---- stage luts2 slice: pair-interleaved, level-5 pairs as (a, b-a) ----
    for (int i = tid; i < NPAIR * (NLUT / 4); i += BTHREADS) {
        const int p = i >> 4, q = i & 15;
        float4 a = __ldg((const float4*)(luts2 + (obase + p) * NLUT) + q);
        float4 b = __ldg((const float4*)(luts2 + (obase + NPAIR + p) * NLUT) + q);
        unsigned long long* d = s_l2p + p * L2PS + q * 4;
        d[0] = pk2(a.x, b.x);
        d[1] = pk2(a.y - a.x, b.y - b.x);
        d[2] = pk2(a.z, b.z);
        d[3] = pk2(a.w - a.z, b.w - b.z);
    }
    for (int i = tid; i < B_OUT * 6; i += BTHREADS)
        s_idx[i] = __ldg(idx2 + obase * 6 + i);
    __syncthreads();

    if (tid < RG * NPAIR) {                  // 400 compute threads
        const int p = tid >> 3;              // pair id (8 lanes share)
        const int r = tid & 7;               // row within group
        const unsigned long long* Lp = s_l2p + p * L2PS;
        const float* h1g = g_h1 + (size_t)g * O1 * RG + r;
        const int* ipA = s_idx + p * 6;
        const int* ipB = s_idx + (p + NPAIR) * 6;

        // prefetch x5..x2 (x1, x0 loaded lazily to cap live registers)
        unsigned long long xp5, xp4, xn4, xp3, xn3, xp2, xn2;
        {
            float a, b;
            a = __ldg(h1g + ipA[5] * RG); b = __ldg(h1g + ipB[5] * RG);
            xp5 = pk2(a, b);
            a = __ldg(h1g + ipA[4] * RG); b = __ldg(h1g + ipB[4] * RG);
            xp4 = pk2(a, b); xn4 = pk2(-a, -b);
            a = __ldg(h1g + ipA[3] * RG); b = __ldg(h1g + ipB[3] * RG);
            xp3 = pk2(a, b); xn3 = pk2(-a, -b);
            a = __ldg(h1g + ipA[2] * RG); b = __ldg(h1g + ipB[2] * RG);
            xp2 = pk2(a, b); xn2 = pk2(-a, -b);
        }

        // levels x5..x2 per 16-block -> u[4]
        unsigned long long u[4];
        #pragma unroll
        for (int t = 0; t < 4; t++) {
            const unsigned long long* Lt = Lp + 16 * t;
            ulonglong2 c;
            unsigned long long w0, w1, v0, v1, h0, h1v;
            c = *(const ulonglong2*)(Lt + 0);  w0 = fma2(xp5, c.y, c.x);
            c = *(const ulonglong2*)(Lt + 2);  w1 = fma2(xp5, c.y, c.x);
            v0 = lerp2(w0, w1, xp4, xn4);
            c = *(const ulonglong2*)(Lt + 4);  w0 = fma2(xp5, c.y, c.x);
            c = *(const ulonglong2*)(Lt + 6);  w1 = fma2(xp5, c.y, c.x);
            v1 = lerp2(w0, w1, xp4, xn4);
            h0 = lerp2(v0, v1, xp3, xn3);
            c = *(const ulonglong2*)(Lt + 8);  w0 = fma2(xp5, c.y, c.x);
            c = *(const ulonglong2*)(Lt + 10); w1 = fma2(xp5, c.y, c.x);
            v0 = lerp2(w0, w1, xp4, xn4);
            c = *(const ulonglong2*)(Lt + 12); w0 = fma2(xp5, c.y, c.x);
            c = *(const ulonglong2*)(Lt + 14); w1 = fma2(xp5, c.y, c.x);
            v1 = lerp2(w0, w1, xp4, xn4);
            h1v = lerp2(v0, v1, xp3, xn3);
            u[t] = lerp2(h0, h1v, xp2, xn2);
        }
        // tail: x1 then x0 (lazy loads)
        float a1, b1;
        a1 = __ldg(h1g + ipA[1] * RG); b1 = __ldg(h1g + ipB[1] * RG);
        unsigned long long xp1 = pk2(a1, b1), xn1 = pk2(-a1, -b1);
        unsigned long long t0 = lerp2(u[0], u[1], xp1, xn1);
        unsigned long long t1 = lerp2(u[2], u[3], xp1, xn1);
        a1 = __ldg(h1g + ipA[0] * RG); b1 = __ldg(h1g + ipB[0] * RG);
        unsigned long long xp0 = pk2(a1, b1), xn0 = pk2(-a1, -b1);
        unsigned long long res = lerp2(t0, t1, xp0, xn0);

        float hA, hB;
        upk2(hA, hB, res);
        s_h2[p * RG + r]           = hA;
        s_h2[(p + NPAIR) * RG + r] = hB;
    }
    __syncthreads();

    // ---- deterministic fixed-order class sum: 1 class x 8 rows ----
    if (tid < RG) {
        const float* hp = s_h2 + tid;
        float s0 = 0.f, s1 = 0.f;
        #pragma unroll 4
        for (int j = 0; j < B_OUT; j += 2) {
            s0 += hp[(j + 0) * RG];
            s1 += hp[(j + 1) * RG];
        }
        out[(g * RG + tid) * NCLS + os] = (s0 + s1) / TAU;
    }
}

// ================== launch ==================
extern "C" void kernel_launch(void* const* d_in, const int* in_sizes, int n_in,
                              void* d_out, int out_size)
{
    const float* x      = (const float*)d_in[0];
    const float* thr    = (const float*)d_in[1];
    const float* luts1  = (const float*)d_in[2];
    const int*   idx1   = (const int*)  d_in[3];
    const float* luts2  = (const float*)d_in[4];
    const int*   idx2   = (const int*)  d_in[5];
    float*       out    = (float*)d_out;

    const int smemB = NPAIR * L2PS * 8 + B_OUT * 6 * 4 + B_OUT * RG * 4;
    static bool attr_set = false;
    if (!attr_set) {
        cudaFuncSetAttribute(kB_layer2, cudaFuncAttributeMaxDynamicSharedMemorySize, smemB);
        attr_set = true;
    }

    k01_layer1<<<NG * A_OSPL, 512>>>(x, thr, luts1, idx1);
    kB_layer2<<<NG * B_OSPL, BTHREADS, smemB>>>(luts2, idx2, out);
}

// round 11
// speedup vs baseline: 1.0880x; 1.0784x over previous
#include <cuda_runtime.h>

// ---------------- Problem constants ----------------
#define BATCH    512
#define FEAT     1024
#define O1       2000
#define O2       1000
#define NLUT     64
#define NCLS     10
#define TAU      3.3333333f

#define RG       8                  // kB row group (g_h1 layout)
#define NG       (BATCH / RG)       // 64

// kA: 4-row subgroups x 4 output slices -> 512 CTAs, thermo redundancy 4x
#define RGA      4
#define NSG      (BATCH / RGA)      // 128 subgroups
#define A_OSPL   4
#define A_OUT    (O1 / A_OSPL)      // 500

// kB (R7/R10 config, measured 12.64us): 640 CTAs, 4 CTAs/SM
#define B_OSPL   10
#define B_OUT    (O2 / B_OSPL)      // 100 = 1 class
#define NPAIR    (B_OUT / 2)        // 50
#define L2PS     66                 // padded u64 stride per LUT pair
#define BTHREADS 448

// ---------------- Device scratch ----------------
__device__ float g_h1[NG * O1 * RG];      // 4 MB, layout [g8][o][r], r in 0..7

// ---------------- f32x2 helpers ----------------
__device__ __forceinline__ unsigned long long pk2(float lo, float hi) {
    unsigned long long r;
    asm("mov.b64 %0, {%1, %2};" : "=l"(r) : "f"(lo), "f"(hi));
    return r;
}
__device__ __forceinline__ void upk2(float& lo, float& hi, unsigned long long v) {
    asm("mov.b64 {%0, %1}, %2;" : "=f"(lo), "=f"(hi) : "l"(v));
}
__device__ __forceinline__ unsigned long long fma2(unsigned long long a,
                                                   unsigned long long b,
                                                   unsigned long long c) {
    unsigned long long d;
    asm("fma.rn.f32x2 %0, %1, %2, %3;" : "=l"(d) : "l"(a), "l"(b), "l"(c));
    return d;
}
__device__ __forceinline__ unsigned long long lerp2(unsigned long long a,
                                                    unsigned long long b,
                                                    unsigned long long x,
                                                    unsigned long long nx) {
    return fma2(x, b, fma2(nx, a, a));
}

// ============ Kernel 1: thermometer (4 rows) + layer 1 gather ============
// grid 128*4 = 512 CTAs, 512 threads. Half the thermo redundancy of R10's
// 512-CTA config, same gather parallelism. Writes kB's RG=8 g_h1 layout.
__global__ __launch_bounds__(512)
void k01_layer1(const float* __restrict__ x,     const float* __restrict__ thr,
                const float* __restrict__ luts1, const int* __restrict__ idx1)
{
    __shared__ float    s_thr[FEAT * 3];      // 12 KB
    __shared__ unsigned s_bits[RGA * 97];     // 1.6 KB
    __shared__ int      s_idx[A_OUT * 6];     // 12 KB

    const int sg    = blockIdx.x >> 2;        // 4-row subgroup, 0..127
    const int os    = blockIdx.x & 3;
    const int obase = os * A_OUT;
    const int g8    = sg >> 1;                // 8-row group for g_h1
    const int rbase = (sg & 1) * RGA;         // 0 or 4 within the 8-row group
    const int tid   = threadIdx.x;
    const int lane  = tid & 31;

    for (int i = tid; i < FEAT * 3 / 4; i += 512)
        ((float4*)s_thr)[i] = __ldg((const float4*)thr + i);
    for (int i = tid; i < A_OUT * 6; i += 512)
        s_idx[i] = __ldg(idx1 + obase * 6 + i);
    __syncthreads();

    // thermometer: 4 rows x 1024 features
    for (int i = tid; i < RGA * FEAT; i += 512) {
        const int r = i >> 10;
        const int f = i & 1023;
        float xv = __ldg(x + (sg * RGA + r) * FEAT + f);
        float t0 = s_thr[f * 3 + 0];
        float t1 = s_thr[f * 3 + 1];
        float t2 = s_thr[f * 3 + 2];
        unsigned b0 = __ballot_sync(0xFFFFFFFFu, xv > t0);
        unsigned b1 = __ballot_sync(0xFFFFFFFFu, xv > t1);
        unsigned b2 = __ballot_sync(0xFFFFFFFFu, xv > t2);
        if (lane == 0) {
            unsigned* wp = s_bits + r * 97 + (f >> 5);
            wp[0]  = b0;
            wp[32] = b1;
            wp[64] = b2;
        }
    }
    __syncthreads();

    // layer 1 gather: task t -> (o = t>>2, r4 = t&3)
    #pragma unroll 2
    for (int t = tid; t < A_OUT * RGA; t += 512) {
        const int ol = t >> 2;
        const int r4 = t & 3;
        const unsigned* bp = s_bits + r4 * 97;
        int code = 0;
        #pragma unroll
        for (int k = 0; k < 6; k++) {
            unsigned i  = (unsigned)s_idx[ol * 6 + k];
            unsigned f  = i / 3u;
            unsigned tt = i - f * 3u;
            unsigned wv = bp[tt * 32 + (f >> 5)];
            code = (code << 1) | (int)((wv >> (f & 31)) & 1u);
        }
        g_h1[(g8 * O1 + obase + ol) * RG + rbase + r4] =
            __ldg(luts1 + (obase + ol) * NLUT + code);
    }
}

// ============ Kernel 2: layer 2 interp + one class sum per CTA ============
// Exact R10 configuration (measured 12.64us) — unchanged.
__global__ __launch_bounds__(BTHREADS, 4)
void kB_layer2(const float* __restrict__ luts2, const int* __restrict__ idx2,
               float* __restrict__ out)
{
    extern __shared__ char smem[];
    unsigned long long* s_l2p = (unsigned long long*)smem;        // 50*66 u64
    int*                s_idx = (int*)(s_l2p + NPAIR * L2PS);     // 600 i
    float*              s_h2  = (float*)(s_idx + B_OUT * 6);      // 800 f

    const int g     = blockIdx.x / B_OSPL;
    const int os    = blockIdx.x % B_OSPL;
    const int obase = os * B_OUT;
    const int tid   = threadIdx.x;

    for (int i = tid; i < NPAIR * (NLUT / 4); i += BTHREADS) {
        const int p = i >> 4, q = i & 15;
        float4 a = __ldg((const float4*)(luts2 + (obase + p) * NLUT) + q);
        float4 b = __ldg((const float4*)(luts2 + (obase + NPAIR + p) * NLUT) + q);
        unsigned long long* d = s_l2p + p * L2PS + q * 4;
        d[0] = pk2(a.x, b.x);
        d[1] = pk2(a.y - a.x, b.y - b.x);
        d[2] = pk2(a.z, b.z);
        d[3] = pk2(a.w - a.z, b.w - b.z);
    }
    for (int i = tid; i < B_OUT * 6; i += BTHREADS)
        s_idx[i] = __ldg(idx2 + obase * 6 + i);
    __syncthreads();

    if (tid < RG * NPAIR) {                  // 400 compute threads
        const int p = tid >> 3;
        const int r = tid & 7;
        const unsigned long long* Lp = s_l2p + p * L2PS;
        const float* h1g = g_h1 + (size_t)g * O1 * RG + r;
        const int* ipA = s_idx + p * 6;
        const int* ipB = s_idx + (p + NPAIR) * 6;

        unsigned long long xp5, xp4, xn4, xp3, xn3, xp2, xn2;
        {
            float a, b;
            a = __ldg(h1g + ipA[5] * RG); b = __ldg(h1g + ipB[5] * RG);
            xp5 = pk2(a, b);
            a = __ldg(h1g + ipA[4] * RG); b = __ldg(h1g + ipB[4] * RG);
            xp4 = pk2(a, b); xn4 = pk2(-a, -b);
            a = __ldg(h1g + ipA[3] * RG); b = __ldg(h1g + ipB[3] * RG);
            xp3 = pk2(a, b); xn3 = pk2(-a, -b);
            a = __ldg(h1g + ipA[2] * RG); b = __ldg(h1g + ipB[2] * RG);
            xp2 = pk2(a, b); xn2 = pk2(-a, -b);
        }

        unsigned long long u[4];
        #pragma unroll
        for (int t = 0; t < 4; t++) {
            const unsigned long long* Lt = Lp + 16 * t;
            ulonglong2 c;
            unsigned long long w0, w1, v0, v1, h0, h1v;
            c = *(const ulonglong2*)(Lt + 0);  w0 = fma2(xp5, c.y, c.x);
            c = *(const ulonglong2*)(Lt + 2);  w1 = fma2(xp5, c.y, c.x);
            v0 = lerp2(w0, w1, xp4, xn4);
            c = *(const ulonglong2*)(Lt + 4);  w0 = fma2(xp5, c.y, c.x);
            c = *(const ulonglong2*)(Lt + 6);  w1 = fma2(xp5, c.y, c.x);
            v1 = lerp2(w0, w1, xp4, xn4);
            h0 = lerp2(v0, v1, xp3, xn3);
            c = *(const ulonglong2*)(Lt + 8);  w0 = fma2(xp5, c.y, c.x);
            c = *(const ulonglong2*)(Lt + 10); w1 = fma2(xp5, c.y, c.x);
            v0 = lerp2(w0, w1, xp4, xn4);
            c = *(const ulonglong2*)(Lt + 12); w0 = fma2(xp5, c.y, c.x);
            c = *(const ulonglong2*)(Lt + 14); w1 = fma2(xp5, c.y, c.x);
            v1 = lerp2(w0, w1, xp4, xn4);
            h1v = lerp2(v0, v1, xp3, xn3);
            u[t] = lerp2(h0, h1v, xp2, xn2);
        }
        float a1, b1;
        a1 = __ldg(h1g + ipA[1] * RG); b1 = __ldg(h1g + ipB[1] * RG);
        unsigned long long xp1 = pk2(a1, b1), xn1 = pk2(-a1, -b1);
        unsigned long long t0 = lerp2(u[0], u[1], xp1, xn1);
        unsigned long long t1 = lerp2(u[2], u[3], xp1, xn1);
        a1 = __ldg(h1g + ipA[0] * RG); b1 = __ldg(h1g + ipB[0] * RG);
        unsigned long long xp0 = pk2(a1, b1), xn0 = pk2(-a1, -b1);
        unsigned long long res = lerp2(t0, t1, xp0, xn0);

        float hA, hB;
        upk2(hA, hB, res);
        s_h2[p * RG + r]           = hA;
        s_h2[(p + NPAIR) * RG + r] = hB;
    }
    __syncthreads();

    if (tid < RG) {
        const float* hp = s_h2 + tid;
        float s0 = 0.f, s1 = 0.f;
        #pragma unroll 4
        for (int j = 0; j < B_OUT; j += 2) {
            s0 += hp[(j + 0) * RG];
            s1 += hp[(j + 1) * RG];
        }
        out[(g * RG + tid) * NCLS + os] = (s0 + s1) / TAU;
    }
}

// ================== launch ==================
extern "C" void kernel_launch(void* const* d_in, const int* in_sizes, int n_in,
                              void* d_out, int out_size)
{
    const float* x      = (const float*)d_in[0];
    const float* thr    = (const float*)d_in[1];
    const float* luts1  = (const float*)d_in[2];
    const int*   idx1   = (const int*)  d_in[3];
    const float* luts2  = (const float*)d_in[4];
    const int*   idx2   = (const int*)  d_in[5];
    float*       out    = (float*)d_out;

    const int smemB = NPAIR * L2PS * 8 + B_OUT * 6 * 4 + B_OUT * RG * 4;
    static bool attr_set = false;
    if (!attr_set) {
        cudaFuncSetAttribute(kB_layer2, cudaFuncAttributeMaxDynamicSharedMemorySize, smemB);
        attr_set = true;
    }

    k01_layer1<<<NSG * A_OSPL, 512>>>(x, thr, luts1, idx1);
    kB_layer2<<<NG * B_OSPL, BTHREADS, smemB>>>(luts2, idx2, out);
}